// round 1
// baseline (speedup 1.0000x reference)
#include <cuda_runtime.h>
#include <math.h>

#define Bb 4
#define Nn 1024
#define Dd 1024
#define Ee 32
#define Hh 4096

// ---------------- scratch (device globals; no allocation allowed) ----------
__device__ float g_q[Ee * Dd];             // [e][d]
__device__ float g_logits[Bb * Nn * Ee];   // [b][n][e]
__device__ float g_dispatch[Bb * Nn * Ee]; // [b][n][e]
__device__ float g_combine[Bb * Nn * Ee];  // [b][n][e]
__device__ float g_part[Bb * 16 * Ee * Dd];// [b][chunk][e][d]  slots partials
__device__ float g_slots[Bb * Ee * Dd];    // [b][e][d]
__device__ float g_hbuf[Bb * Ee * Hh];     // [b][e][h]
__device__ float g_p2[4 * Bb * Ee * Dd];   // [hc][b][e][d]  mlp2 partials
__device__ float g_rC[Bb * Nn];            // r^2 per (b,n) for combine metric
__device__ float g_diagC[Bb * Ee];         // diag terms (n<32)
__device__ float g_rD[Bb * Ee];            // r^2 per (b,e) for dispatch metric

// ---------------- helpers ----------------
__device__ __forceinline__ float block_sum256(float v, float* red, int t) {
    #pragma unroll
    for (int o = 16; o; o >>= 1) v += __shfl_xor_sync(0xffffffffu, v, o);
    __syncthreads();
    if ((t & 31) == 0) red[t >> 5] = v;
    __syncthreads();
    float s = 0.f;
    #pragma unroll
    for (int i = 0; i < 8; i++) s += red[i];
    return s;
}

__device__ __forceinline__ float block_max256(float v, float* red, int t) {
    #pragma unroll
    for (int o = 16; o; o >>= 1) v = fmaxf(v, __shfl_xor_sync(0xffffffffu, v, o));
    __syncthreads();
    if ((t & 31) == 0) red[t >> 5] = v;
    __syncthreads();
    float s = -INFINITY;
    #pragma unroll
    for (int i = 0; i < 8; i++) s = fmaxf(s, red[i]);
    return s;
}

__device__ __forceinline__ float gelu_exact(float z) {
    return 0.5f * z * (1.0f + erff(z * 0.70710678118654752f));
}

// ---------------- K1: q = LayerNorm(phi*qg+qb)*scale ----------------
__global__ __launch_bounds__(256) void q_kernel(
    const float* __restrict__ phi, const float* __restrict__ qg,
    const float* __restrict__ qb, const float* __restrict__ lng,
    const float* __restrict__ lnb, const float* __restrict__ scp) {
    int e = blockIdx.x, t = threadIdx.x;
    __shared__ float red[8];
    float v[4];
    #pragma unroll
    for (int i = 0; i < 4; i++) {
        int d = t + 256 * i;
        v[i] = phi[e * Dd + d] * qg[d] + qb[d];
    }
    float s = v[0] + v[1] + v[2] + v[3];
    float mean = block_sum256(s, red, t) * (1.0f / Dd);
    float sq = 0.f;
    #pragma unroll
    for (int i = 0; i < 4; i++) { float c = v[i] - mean; sq += c * c; }
    float var = block_sum256(sq, red, t) * (1.0f / Dd);
    float inv = rsqrtf(var + 1e-5f);
    float sc = *scp;
    #pragma unroll
    for (int i = 0; i < 4; i++) {
        int d = t + 256 * i;
        g_q[e * Dd + d] = ((v[i] - mean) * inv * lng[d] + lnb[d]) * sc;
    }
}

// ---------------- K2: logits = (x*kg+kb) . q^T  + combine softmax ----------
// block = 32 n-rows of one batch; 256 thr = (e=tx 0..31) x (ty 0..7, 4 n each)
__global__ __launch_bounds__(256) void logits_kernel(
    const float* __restrict__ x, const float* __restrict__ kg,
    const float* __restrict__ kb) {
    int tile = blockIdx.x;         // 128 tiles
    int b = tile >> 5, n0 = (tile & 31) * 32;
    int t = threadIdx.x, tx = t & 31, ty = t >> 5;
    __shared__ float xs[32][65];
    __shared__ float qs[32][65];
    __shared__ float ls[32][33];
    float acc[4] = {0.f, 0.f, 0.f, 0.f};
    for (int dc = 0; dc < 16; dc++) {
        int dbase = dc * 64;
        #pragma unroll
        for (int i = 0; i < 8; i++) {
            int idx = t + 256 * i;
            int r = idx >> 6, c = idx & 63, d = dbase + c;
            xs[r][c] = x[(b * Nn + n0 + r) * Dd + d] * kg[d] + kb[d];
            qs[r][c] = g_q[r * Dd + d];
        }
        __syncthreads();
        #pragma unroll 8
        for (int d = 0; d < 64; d++) {
            float qv = qs[tx][d];
            acc[0] += xs[ty][d] * qv;
            acc[1] += xs[ty + 8][d] * qv;
            acc[2] += xs[ty + 16][d] * qv;
            acc[3] += xs[ty + 24][d] * qv;
        }
        __syncthreads();
    }
    #pragma unroll
    for (int k = 0; k < 4; k++) {
        int r = ty + 8 * k;
        ls[r][tx] = acc[k];
        g_logits[(b * Nn + n0 + r) * Ee + tx] = acc[k];
    }
    __syncthreads();
    // combine softmax over 32 slots: warp per row (8 warps x 4 rows)
    int w = t >> 5, lane = t & 31;
    #pragma unroll
    for (int j = 0; j < 4; j++) {
        int row = w * 4 + j;
        float v = ls[row][lane];
        float m = v;
        #pragma unroll
        for (int o = 16; o; o >>= 1) m = fmaxf(m, __shfl_xor_sync(0xffffffffu, m, o));
        float p = expf(v - m);
        float sden = p;
        #pragma unroll
        for (int o = 16; o; o >>= 1) sden += __shfl_xor_sync(0xffffffffu, sden, o);
        float cw = p / sden;
        int gn = n0 + row;
        g_combine[(b * Nn + gn) * Ee + lane] = cw;
        float sq = cw * cw;
        #pragma unroll
        for (int o = 16; o; o >>= 1) sq += __shfl_xor_sync(0xffffffffu, sq, o);
        float r2 = 1.0f / (sq + 1e-9f);   // (rsqrt(ssq+eps))^2
        if (lane == 0) g_rC[b * Nn + gn] = r2;
        if (gn < Ee && lane == gn) g_diagC[b * Ee + gn] = cw * r2;
    }
}

// ---------------- K3: dispatch softmax over N per (b,e) ----------------
__global__ __launch_bounds__(256) void dispatch_kernel() {
    int e = blockIdx.x, b = blockIdx.y, t = threadIdx.x;
    __shared__ float red[8];
    float v[4];
    #pragma unroll
    for (int i = 0; i < 4; i++)
        v[i] = g_logits[(b * Nn + t + 256 * i) * Ee + e];
    float m = fmaxf(fmaxf(v[0], v[1]), fmaxf(v[2], v[3]));
    m = block_max256(m, red, t);
    float p[4], s = 0.f;
    #pragma unroll
    for (int i = 0; i < 4; i++) { p[i] = expf(v[i] - m); s += p[i]; }
    s = block_sum256(s, red, t);
    float inv = 1.0f / s, ssq = 0.f;
    #pragma unroll
    for (int i = 0; i < 4; i++) {
        float dp = p[i] * inv;
        g_dispatch[(b * Nn + t + 256 * i) * Ee + e] = dp;
        ssq += dp * dp;
    }
    ssq = block_sum256(ssq, red, t);
    if (t == 0) g_rD[b * Ee + e] = 1.0f / (ssq + 1e-9f);
}

// ---------------- K4: slots partials: [b][chunk][e][d] ----------------
__global__ __launch_bounds__(128) void slots_partial_kernel(const float* __restrict__ x) {
    int dt = blockIdx.x, ch = blockIdx.y, b = blockIdx.z;
    int t = threadIdx.x;
    int d = dt * 128 + t, n0 = ch * 64;
    __shared__ float ds[64][32];
    #pragma unroll
    for (int i = 0; i < 16; i++) {
        int idx = t + 128 * i;
        ds[idx >> 5][idx & 31] = g_dispatch[(b * Nn + n0 + (idx >> 5)) * Ee + (idx & 31)];
    }
    __syncthreads();
    float acc[32];
    #pragma unroll
    for (int e = 0; e < 32; e++) acc[e] = 0.f;
    for (int r = 0; r < 64; r++) {
        float xv = x[(b * Nn + n0 + r) * Dd + d];
        #pragma unroll
        for (int e = 0; e < 32; e++) acc[e] += ds[r][e] * xv;
    }
    #pragma unroll
    for (int e = 0; e < 32; e++)
        g_part[((b * 16 + ch) * Ee + e) * Dd + d] = acc[e];
}

// ---------------- K5: reduce slots partials ----------------
__global__ __launch_bounds__(256) void slots_reduce_kernel() {
    int base = blockIdx.x * 1024 + threadIdx.x;
    #pragma unroll
    for (int i = 0; i < 4; i++) {
        int o = base + i * 256;
        int b = o >> 15, ed = o & 32767;
        float s = 0.f;
        #pragma unroll
        for (int c = 0; c < 16; c++) s += g_part[(b * 16 + c) * 32768 + ed];
        g_slots[o] = s;
    }
}

// ---------------- K6: h = gelu(slots @ w1 + b1) ----------------
// grid (H/1024, E); 256 thr, thread owns 4 consecutive h; acc[b][j]
__global__ __launch_bounds__(256) void mlp1_kernel(
    const float* __restrict__ w1, const float* __restrict__ b1) {
    int e = blockIdx.y;
    int h0 = blockIdx.x * 1024;
    int t = threadIdx.x;
    __shared__ float ss[4][1024];
    #pragma unroll
    for (int i = 0; i < 16; i++) {
        int idx = t + 256 * i;
        ss[idx >> 10][idx & 1023] = g_slots[((idx >> 10) * Ee + e) * Dd + (idx & 1023)];
    }
    __syncthreads();
    int hh = h0 + (t << 2);
    float a0x=0,a0y=0,a0z=0,a0w=0, a1x=0,a1y=0,a1z=0,a1w=0;
    float a2x=0,a2y=0,a2z=0,a2w=0, a3x=0,a3y=0,a3z=0,a3w=0;
    const float4* wp = (const float4*)(w1 + (size_t)e * Dd * Hh + hh);
    #pragma unroll 8
    for (int d = 0; d < 1024; d++) {
        float4 w = wp[(size_t)d * (Hh / 4)];
        float s0 = ss[0][d], s1 = ss[1][d], s2 = ss[2][d], s3 = ss[3][d];
        a0x += s0 * w.x; a0y += s0 * w.y; a0z += s0 * w.z; a0w += s0 * w.w;
        a1x += s1 * w.x; a1y += s1 * w.y; a1z += s1 * w.z; a1w += s1 * w.w;
        a2x += s2 * w.x; a2y += s2 * w.y; a2z += s2 * w.z; a2w += s2 * w.w;
        a3x += s3 * w.x; a3y += s3 * w.y; a3z += s3 * w.z; a3w += s3 * w.w;
    }
    float4 bv = *(const float4*)(b1 + e * Hh + hh);
    float4 o;
    o.x = gelu_exact(a0x + bv.x); o.y = gelu_exact(a0y + bv.y);
    o.z = gelu_exact(a0z + bv.z); o.w = gelu_exact(a0w + bv.w);
    *(float4*)&g_hbuf[(0 * Ee + e) * Hh + hh] = o;
    o.x = gelu_exact(a1x + bv.x); o.y = gelu_exact(a1y + bv.y);
    o.z = gelu_exact(a1z + bv.z); o.w = gelu_exact(a1w + bv.w);
    *(float4*)&g_hbuf[(1 * Ee + e) * Hh + hh] = o;
    o.x = gelu_exact(a2x + bv.x); o.y = gelu_exact(a2y + bv.y);
    o.z = gelu_exact(a2z + bv.z); o.w = gelu_exact(a2w + bv.w);
    *(float4*)&g_hbuf[(2 * Ee + e) * Hh + hh] = o;
    o.x = gelu_exact(a3x + bv.x); o.y = gelu_exact(a3y + bv.y);
    o.z = gelu_exact(a3z + bv.z); o.w = gelu_exact(a3w + bv.w);
    *(float4*)&g_hbuf[(3 * Ee + e) * Hh + hh] = o;
}

// ---------------- K7: mlp2 partials over h-chunks ----------------
// grid (4 h-chunks, E); 256 thr, thread owns 4 consecutive d
__global__ __launch_bounds__(256) void mlp2_kernel(const float* __restrict__ w2) {
    int e = blockIdx.y;
    int hc = blockIdx.x;
    int t = threadIdx.x;
    __shared__ float hs[4][1024];
    #pragma unroll
    for (int i = 0; i < 16; i++) {
        int idx = t + 256 * i;
        hs[idx >> 10][idx & 1023] = g_hbuf[((idx >> 10) * Ee + e) * Hh + hc * 1024 + (idx & 1023)];
    }
    __syncthreads();
    int dd = t << 2;
    float a0x=0,a0y=0,a0z=0,a0w=0, a1x=0,a1y=0,a1z=0,a1w=0;
    float a2x=0,a2y=0,a2z=0,a2w=0, a3x=0,a3y=0,a3z=0,a3w=0;
    const float4* wp = (const float4*)(w2 + (size_t)e * Hh * Dd + (size_t)hc * 1024 * Dd + dd);
    #pragma unroll 8
    for (int hl = 0; hl < 1024; hl++) {
        float4 w = wp[(size_t)hl * (Dd / 4)];
        float h0v = hs[0][hl], h1v = hs[1][hl], h2v = hs[2][hl], h3v = hs[3][hl];
        a0x += h0v * w.x; a0y += h0v * w.y; a0z += h0v * w.z; a0w += h0v * w.w;
        a1x += h1v * w.x; a1y += h1v * w.y; a1z += h1v * w.z; a1w += h1v * w.w;
        a2x += h2v * w.x; a2y += h2v * w.y; a2z += h2v * w.z; a2w += h2v * w.w;
        a3x += h3v * w.x; a3y += h3v * w.y; a3z += h3v * w.z; a3w += h3v * w.w;
    }
    float4 v;
    v.x=a0x; v.y=a0y; v.z=a0z; v.w=a0w; *(float4*)&g_p2[((hc*4+0)*Ee+e)*Dd+dd] = v;
    v.x=a1x; v.y=a1y; v.z=a1z; v.w=a1w; *(float4*)&g_p2[((hc*4+1)*Ee+e)*Dd+dd] = v;
    v.x=a2x; v.y=a2y; v.z=a2z; v.w=a2w; *(float4*)&g_p2[((hc*4+2)*Ee+e)*Dd+dd] = v;
    v.x=a3x; v.y=a3y; v.z=a3z; v.w=a3w; *(float4*)&g_p2[((hc*4+3)*Ee+e)*Dd+dd] = v;
}

// ---------------- K8: out = combine @ expert_out ----------------
// grid (D/128, N/64, B); 256 thr = 16 dthr x 16 nthr, each 4n x 8d
__global__ __launch_bounds__(256) void combine_kernel(
    const float* __restrict__ b2, float* __restrict__ out) {
    int b = blockIdx.z;
    int n0 = blockIdx.y * 64;
    int d0 = blockIdx.x * 128;
    int t = threadIdx.x;
    __shared__ float eo[32][128];
    __shared__ float cs[64][33];
    #pragma unroll
    for (int i = 0; i < 16; i++) {
        int idx = t + 256 * i;
        int e = idx >> 7, dl = idx & 127, d = d0 + dl;
        float v = b2[e * Dd + d];
        #pragma unroll
        for (int hc = 0; hc < 4; hc++) v += g_p2[((hc * 4 + b) * Ee + e) * Dd + d];
        eo[e][dl] = v;
    }
    #pragma unroll
    for (int i = 0; i < 8; i++) {
        int idx = t + 256 * i;
        int r = idx >> 5, e = idx & 31;
        cs[r][e] = g_combine[(b * Nn + n0 + r) * Ee + e];
    }
    __syncthreads();
    int dt = t & 15, nt = t >> 4;
    float acc[4][8];
    #pragma unroll
    for (int i = 0; i < 4; i++)
        #pragma unroll
        for (int j = 0; j < 8; j++) acc[i][j] = 0.f;
    #pragma unroll 4
    for (int e = 0; e < 32; e++) {
        float cv[4], ev[8];
        #pragma unroll
        for (int i = 0; i < 4; i++) cv[i] = cs[nt + 16 * i][e];
        #pragma unroll
        for (int j = 0; j < 8; j++) ev[j] = eo[e][dt + 16 * j];
        #pragma unroll
        for (int i = 0; i < 4; i++)
            #pragma unroll
            for (int j = 0; j < 8; j++) acc[i][j] += cv[i] * ev[j];
    }
    #pragma unroll
    for (int i = 0; i < 4; i++) {
        int n = n0 + nt + 16 * i;
        #pragma unroll
        for (int j = 0; j < 8; j++)
            out[(b * Nn + n) * Dd + d0 + dt + 16 * j] = acc[i][j];
    }
}

// ---------------- K9: metrics ----------------
__global__ __launch_bounds__(256) void metrics_kernel(float* __restrict__ out, int moff) {
    int t = threadIdx.x;
    __shared__ float red[8];
    float s = 0.f;
    #pragma unroll
    for (int i = 0; i < 16; i++) s += g_rC[t + 256 * i];
    float sumR2 = block_sum256(s, red, t);
    float sd = (t < Bb * Ee) ? g_diagC[t] : 0.f;
    float sumDiag = block_sum256(sd, red, t);
    float s2 = (t < Bb * Ee) ? g_rD[t] : 0.f;
    float sumD2 = block_sum256(s2, red, t);
    float s0 = (t < Bb) ? g_rD[t * Ee] : 0.f;
    float sumD0 = block_sum256(s0, red, t);
    if (t == 0) {
        out[moff]     = (sumR2 - sumDiag) / (float)(Bb * Nn * (Nn - 1));
        out[moff + 1] = (sumD2 - sumD0) / (float)(Bb * Ee * (Ee * 1 - 1));
    }
}

// ---------------- launch ----------------
extern "C" void kernel_launch(void* const* d_in, const int* in_sizes, int n_in,
                              void* d_out, int out_size) {
    const float* x   = (const float*)d_in[0];
    const float* phi = (const float*)d_in[1];
    const float* kg  = (const float*)d_in[2];
    const float* kb  = (const float*)d_in[3];
    const float* qg  = (const float*)d_in[4];
    const float* qb  = (const float*)d_in[5];
    const float* lng = (const float*)d_in[6];
    const float* lnb = (const float*)d_in[7];
    const float* sc  = (const float*)d_in[8];
    const float* w1  = (const float*)d_in[9];
    const float* b1  = (const float*)d_in[10];
    const float* w2  = (const float*)d_in[11];
    const float* b2  = (const float*)d_in[12];
    float* out = (float*)d_out;

    q_kernel<<<32, 256>>>(phi, qg, qb, lng, lnb, sc);
    logits_kernel<<<128, 256>>>(x, kg, kb);
    dispatch_kernel<<<dim3(Ee, Bb), 256>>>();
    slots_partial_kernel<<<dim3(8, 16, Bb), 128>>>(x);
    slots_reduce_kernel<<<128, 256>>>();
    mlp1_kernel<<<dim3(4, Ee), 256>>>(w1, b1);
    mlp2_kernel<<<dim3(4, Ee), 256>>>(w2);
    combine_kernel<<<dim3(8, 16, Bb), 256>>>(b2, out);
    metrics_kernel<<<1, 256>>>(out, out_size - 2);
}

// round 3
// speedup vs baseline: 1.8790x; 1.8790x over previous
#include <cuda_runtime.h>
#include <math.h>

#define Bb 4
#define Nn 1024
#define Dd 1024
#define Ee 32
#define Hh 4096

// ---------------- scratch (device globals; no allocation allowed) ----------
__device__ float g_q[Ee * Dd];                  // [e][d]
__device__ float g_logits[Bb * Nn * Ee];        // [b][n][e]
__device__ float g_dispatch[Bb * Nn * Ee];      // [b][n][e]
__device__ float g_combine[Bb * Nn * Ee];       // [b][n][e]
__device__ float g_part[Bb * 32 * Ee * Dd];     // [b][ch32][e][d] slots partials (16MB)
__device__ float g_slots[Bb * Ee * Dd];         // [b][e][d]
__device__ float g_h1p[4 * Bb * Ee * Hh];       // [dz][b][e][h] mlp1 partials (8MB)
__device__ float g_hbuf[Bb * Ee * Hh];          // [b][e][h]
__device__ float g_p2[16 * Bb * Ee * Dd];       // [hc][b][e][d] mlp2 partials (8MB)
__device__ float g_eout[Bb * Ee * Dd];          // [b][e][d] expert outputs (+b2)
__device__ float g_rC[Bb * Nn];                 // r^2 per (b,n) combine metric
__device__ float g_diagC[Bb * Ee];              // diag terms (n<32)
__device__ float g_rD[Bb * Ee];                 // r^2 per (b,e) dispatch metric

// ---------------- helpers ----------------
__device__ __forceinline__ float block_sum256(float v, float* red, int t) {
    #pragma unroll
    for (int o = 16; o; o >>= 1) v += __shfl_xor_sync(0xffffffffu, v, o);
    __syncthreads();
    if ((t & 31) == 0) red[t >> 5] = v;
    __syncthreads();
    float s = 0.f;
    #pragma unroll
    for (int i = 0; i < 8; i++) s += red[i];
    return s;
}

__device__ __forceinline__ float block_max256(float v, float* red, int t) {
    #pragma unroll
    for (int o = 16; o; o >>= 1) v = fmaxf(v, __shfl_xor_sync(0xffffffffu, v, o));
    __syncthreads();
    if ((t & 31) == 0) red[t >> 5] = v;
    __syncthreads();
    float s = -INFINITY;
    #pragma unroll
    for (int i = 0; i < 8; i++) s = fmaxf(s, red[i]);
    return s;
}

__device__ __forceinline__ float gelu_exact(float z) {
    return 0.5f * z * (1.0f + erff(z * 0.70710678118654752f));
}

// ---------------- K1: q = LayerNorm(phi*qg+qb)*scale ----------------
__global__ __launch_bounds__(256) void q_kernel(
    const float* __restrict__ phi, const float* __restrict__ qg,
    const float* __restrict__ qb, const float* __restrict__ lng,
    const float* __restrict__ lnb, const float* __restrict__ scp) {
    int e = blockIdx.x, t = threadIdx.x;
    __shared__ float red[8];
    float v[4];
    #pragma unroll
    for (int i = 0; i < 4; i++) {
        int d = t + 256 * i;
        v[i] = phi[e * Dd + d] * qg[d] + qb[d];
    }
    float s = v[0] + v[1] + v[2] + v[3];
    float mean = block_sum256(s, red, t) * (1.0f / Dd);
    float sq = 0.f;
    #pragma unroll
    for (int i = 0; i < 4; i++) { float c = v[i] - mean; sq += c * c; }
    float var = block_sum256(sq, red, t) * (1.0f / Dd);
    float inv = rsqrtf(var + 1e-5f);
    float sc = *scp;
    #pragma unroll
    for (int i = 0; i < 4; i++) {
        int d = t + 256 * i;
        g_q[e * Dd + d] = ((v[i] - mean) * inv * lng[d] + lnb[d]) * sc;
    }
}

// ---------------- K2: logits = (x*kg+kb) . q^T  + combine softmax ----------
__global__ __launch_bounds__(256) void logits_kernel(
    const float* __restrict__ x, const float* __restrict__ kg,
    const float* __restrict__ kb) {
    int tile = blockIdx.x;         // 128 tiles
    int b = tile >> 5, n0 = (tile & 31) * 32;
    int t = threadIdx.x, tx = t & 31, ty = t >> 5;
    __shared__ float xs[32][65];
    __shared__ float qs[32][65];
    __shared__ float ls[32][33];
    float acc[4] = {0.f, 0.f, 0.f, 0.f};
    for (int dc = 0; dc < 16; dc++) {
        int dbase = dc * 64;
        #pragma unroll
        for (int i = 0; i < 8; i++) {
            int idx = t + 256 * i;
            int r = idx >> 6, c = idx & 63, d = dbase + c;
            xs[r][c] = x[(b * Nn + n0 + r) * Dd + d] * kg[d] + kb[d];
            qs[r][c] = g_q[r * Dd + d];
        }
        __syncthreads();
        #pragma unroll 8
        for (int d = 0; d < 64; d++) {
            float qv = qs[tx][d];
            acc[0] += xs[ty][d] * qv;
            acc[1] += xs[ty + 8][d] * qv;
            acc[2] += xs[ty + 16][d] * qv;
            acc[3] += xs[ty + 24][d] * qv;
        }
        __syncthreads();
    }
    #pragma unroll
    for (int k = 0; k < 4; k++) {
        int r = ty + 8 * k;
        ls[r][tx] = acc[k];
        g_logits[(b * Nn + n0 + r) * Ee + tx] = acc[k];
    }
    __syncthreads();
    int w = t >> 5, lane = t & 31;
    #pragma unroll
    for (int j = 0; j < 4; j++) {
        int row = w * 4 + j;
        float v = ls[row][lane];
        float m = v;
        #pragma unroll
        for (int o = 16; o; o >>= 1) m = fmaxf(m, __shfl_xor_sync(0xffffffffu, m, o));
        float p = expf(v - m);
        float sden = p;
        #pragma unroll
        for (int o = 16; o; o >>= 1) sden += __shfl_xor_sync(0xffffffffu, sden, o);
        float cw = p / sden;
        int gn = n0 + row;
        g_combine[(b * Nn + gn) * Ee + lane] = cw;
        float sq = cw * cw;
        #pragma unroll
        for (int o = 16; o; o >>= 1) sq += __shfl_xor_sync(0xffffffffu, sq, o);
        float r2 = 1.0f / (sq + 1e-9f);
        if (lane == 0) g_rC[b * Nn + gn] = r2;
        if (gn < Ee && lane == gn) g_diagC[b * Ee + gn] = cw * r2;
    }
}

// ---------------- K3: dispatch softmax over N per (b,e) ----------------
__global__ __launch_bounds__(256) void dispatch_kernel() {
    int e = blockIdx.x, b = blockIdx.y, t = threadIdx.x;
    __shared__ float red[8];
    float v[4];
    #pragma unroll
    for (int i = 0; i < 4; i++)
        v[i] = g_logits[(b * Nn + t + 256 * i) * Ee + e];
    float m = fmaxf(fmaxf(v[0], v[1]), fmaxf(v[2], v[3]));
    m = block_max256(m, red, t);
    float p[4], s = 0.f;
    #pragma unroll
    for (int i = 0; i < 4; i++) { p[i] = expf(v[i] - m); s += p[i]; }
    s = block_sum256(s, red, t);
    float inv = 1.0f / s, ssq = 0.f;
    #pragma unroll
    for (int i = 0; i < 4; i++) {
        float dp = p[i] * inv;
        g_dispatch[(b * Nn + t + 256 * i) * Ee + e] = dp;
        ssq += dp * dp;
    }
    ssq = block_sum256(ssq, red, t);
    if (t == 0) g_rD[b * Ee + e] = 1.0f / (ssq + 1e-9f);
}

// ---------------- K4: slots partials: [b][ch32][e][d] ----------------
// grid (4 dt, 32 ch, 4 b); 256 thr; each thread one d, acc over 32 e
__global__ __launch_bounds__(256) void slots_partial_kernel(const float* __restrict__ x) {
    int dt = blockIdx.x, ch = blockIdx.y, b = blockIdx.z;
    int t = threadIdx.x;
    int d = dt * 256 + t, n0 = ch * 32;
    __shared__ __align__(16) float ds[32][32];
    #pragma unroll
    for (int i = 0; i < 4; i++) {
        int idx = t + 256 * i;
        ds[idx >> 5][idx & 31] = g_dispatch[(b * Nn + n0 + (idx >> 5)) * Ee + (idx & 31)];
    }
    __syncthreads();
    float acc[32];
    #pragma unroll
    for (int e = 0; e < 32; e++) acc[e] = 0.f;
    #pragma unroll 2
    for (int r = 0; r < 32; r++) {
        float xv = x[(b * Nn + n0 + r) * Dd + d];
        #pragma unroll
        for (int e4 = 0; e4 < 8; e4++) {
            float4 dv = *(const float4*)&ds[r][e4 * 4];
            acc[e4 * 4 + 0] += dv.x * xv;
            acc[e4 * 4 + 1] += dv.y * xv;
            acc[e4 * 4 + 2] += dv.z * xv;
            acc[e4 * 4 + 3] += dv.w * xv;
        }
    }
    #pragma unroll
    for (int e = 0; e < 32; e++)
        g_part[((b * 32 + ch) * Ee + e) * Dd + d] = acc[e];
}

// ---------------- K5: reduce slots partials (32 chunks) ----------------
__global__ __launch_bounds__(256) void slots_reduce_kernel() {
    int idx4 = blockIdx.x * 256 + threadIdx.x;   // 32768 float4s
    int o = idx4 * 4;
    int b = o >> 15, ed = o & 32767;
    float4 s = make_float4(0.f, 0.f, 0.f, 0.f);
    #pragma unroll
    for (int c = 0; c < 32; c++) {
        float4 p = *(const float4*)&g_part[(b * 32 + c) * 32768 + ed];
        s.x += p.x; s.y += p.y; s.z += p.z; s.w += p.w;
    }
    *(float4*)&g_slots[o] = s;
}

// ---------------- K6: mlp1 partials: h1p[dz][b][e][h] ----------------
// grid (4 h-tiles, E, 4 dz); 256 thr; thread owns 4 consecutive h
__global__ __launch_bounds__(256) void mlp1_kernel(const float* __restrict__ w1) {
    int e = blockIdx.y;
    int h0 = blockIdx.x * 1024;
    int dz = blockIdx.z;
    int t = threadIdx.x;
    __shared__ __align__(16) float ss[256][4];   // [d_local][b]
    #pragma unroll
    for (int i = 0; i < 4; i++) {
        int idx = t + 256 * i;
        int dl = idx >> 2, b = idx & 3;
        ss[dl][b] = g_slots[(b * Ee + e) * Dd + dz * 256 + dl];
    }
    __syncthreads();
    int hh = h0 + (t << 2);
    float4 a0 = make_float4(0.f,0.f,0.f,0.f), a1 = a0, a2 = a0, a3 = a0;
    const float4* wp = (const float4*)(w1 + ((size_t)e * Dd + dz * 256) * Hh + hh);
    #pragma unroll 8
    for (int d = 0; d < 256; d++) {
        float4 w = wp[(size_t)d * (Hh / 4)];
        float4 s = *(const float4*)&ss[d][0];
        a0.x += s.x * w.x; a0.y += s.x * w.y; a0.z += s.x * w.z; a0.w += s.x * w.w;
        a1.x += s.y * w.x; a1.y += s.y * w.y; a1.z += s.y * w.z; a1.w += s.y * w.w;
        a2.x += s.z * w.x; a2.y += s.z * w.y; a2.z += s.z * w.z; a2.w += s.z * w.w;
        a3.x += s.w * w.x; a3.y += s.w * w.y; a3.z += s.w * w.z; a3.w += s.w * w.w;
    }
    *(float4*)&g_h1p[((dz * 4 + 0) * Ee + e) * Hh + hh] = a0;
    *(float4*)&g_h1p[((dz * 4 + 1) * Ee + e) * Hh + hh] = a1;
    *(float4*)&g_h1p[((dz * 4 + 2) * Ee + e) * Hh + hh] = a2;
    *(float4*)&g_h1p[((dz * 4 + 3) * Ee + e) * Hh + hh] = a3;
}

// ---------------- K7: reduce h1 partials + bias + gelu ----------------
__global__ __launch_bounds__(256) void h1_reduce_kernel(const float* __restrict__ b1) {
    int idx4 = blockIdx.x * 256 + threadIdx.x;   // 131072 float4s
    int o = idx4 * 4;                            // over [b][e][h]
    int e = (o >> 12) & 31, h = o & 4095;
    float4 s = *(const float4*)&b1[e * Hh + h];
    #pragma unroll
    for (int dz = 0; dz < 4; dz++) {
        float4 p = *(const float4*)&g_h1p[dz * 524288 + o];
        s.x += p.x; s.y += p.y; s.z += p.z; s.w += p.w;
    }
    float4 g;
    g.x = gelu_exact(s.x); g.y = gelu_exact(s.y);
    g.z = gelu_exact(s.z); g.w = gelu_exact(s.w);
    *(float4*)&g_hbuf[o] = g;
}

// ---------------- K8: mlp2 partials: p2[hc][b][e][d] ----------------
// grid (16 hc, E); 256 thr; thread owns 4 consecutive d
__global__ __launch_bounds__(256) void mlp2_kernel(const float* __restrict__ w2) {
    int e = blockIdx.y;
    int hc = blockIdx.x;
    int t = threadIdx.x;
    __shared__ __align__(16) float hs[256][4];   // [h_local][b]
    #pragma unroll
    for (int i = 0; i < 4; i++) {
        int idx = t + 256 * i;
        int hl = idx >> 2, b = idx & 3;
        hs[hl][b] = g_hbuf[(b * Ee + e) * Hh + hc * 256 + hl];
    }
    __syncthreads();
    int dd = t << 2;
    float4 a0 = make_float4(0.f,0.f,0.f,0.f), a1 = a0, a2 = a0, a3 = a0;
    const float4* wp = (const float4*)(w2 + ((size_t)e * Hh + hc * 256) * Dd + dd);
    #pragma unroll 8
    for (int hl = 0; hl < 256; hl++) {
        float4 w = wp[(size_t)hl * (Dd / 4)];
        float4 s = *(const float4*)&hs[hl][0];
        a0.x += s.x * w.x; a0.y += s.x * w.y; a0.z += s.x * w.z; a0.w += s.x * w.w;
        a1.x += s.y * w.x; a1.y += s.y * w.y; a1.z += s.y * w.z; a1.w += s.y * w.w;
        a2.x += s.z * w.x; a2.y += s.z * w.y; a2.z += s.z * w.z; a2.w += s.z * w.w;
        a3.x += s.w * w.x; a3.y += s.w * w.y; a3.z += s.w * w.z; a3.w += s.w * w.w;
    }
    *(float4*)&g_p2[((hc * 4 + 0) * Ee + e) * Dd + dd] = a0;
    *(float4*)&g_p2[((hc * 4 + 1) * Ee + e) * Dd + dd] = a1;
    *(float4*)&g_p2[((hc * 4 + 2) * Ee + e) * Dd + dd] = a2;
    *(float4*)&g_p2[((hc * 4 + 3) * Ee + e) * Dd + dd] = a3;
}

// ---------------- K9: reduce p2 partials + b2 -> g_eout ----------------
__global__ __launch_bounds__(256) void p2_reduce_kernel(const float* __restrict__ b2) {
    int idx4 = blockIdx.x * 256 + threadIdx.x;   // 32768 float4s
    int o = idx4 * 4;                            // over [b][e][d]
    int e = (o >> 10) & 31, d = o & 1023;
    float4 s = *(const float4*)&b2[e * Dd + d];
    #pragma unroll
    for (int hc = 0; hc < 16; hc++) {
        float4 p = *(const float4*)&g_p2[hc * 131072 + o];
        s.x += p.x; s.y += p.y; s.z += p.z; s.w += p.w;
    }
    *(float4*)&g_eout[o] = s;
}

// ---------------- K10: out = combine @ expert_out ----------------
__global__ __launch_bounds__(256) void combine_kernel(float* __restrict__ out) {
    int b = blockIdx.z;
    int n0 = blockIdx.y * 64;
    int d0 = blockIdx.x * 128;
    int t = threadIdx.x;
    __shared__ float eo[32][128];
    __shared__ float cs[64][33];
    #pragma unroll
    for (int i = 0; i < 16; i++) {
        int idx = t + 256 * i;
        int e = idx >> 7, dl = idx & 127;
        eo[e][dl] = g_eout[(b * Ee + e) * Dd + d0 + dl];
    }
    #pragma unroll
    for (int i = 0; i < 8; i++) {
        int idx = t + 256 * i;
        int r = idx >> 5, e = idx & 31;
        cs[r][e] = g_combine[(b * Nn + n0 + r) * Ee + e];
    }
    __syncthreads();
    int dt = t & 15, nt = t >> 4;
    float acc[4][8];
    #pragma unroll
    for (int i = 0; i < 4; i++)
        #pragma unroll
        for (int j = 0; j < 8; j++) acc[i][j] = 0.f;
    #pragma unroll 4
    for (int e = 0; e < 32; e++) {
        float cv[4], ev[8];
        #pragma unroll
        for (int i = 0; i < 4; i++) cv[i] = cs[nt + 16 * i][e];
        #pragma unroll
        for (int j = 0; j < 8; j++) ev[j] = eo[e][dt + 16 * j];
        #pragma unroll
        for (int i = 0; i < 4; i++)
            #pragma unroll
            for (int j = 0; j < 8; j++) acc[i][j] += cv[i] * ev[j];
    }
    #pragma unroll
    for (int i = 0; i < 4; i++) {
        int n = n0 + nt + 16 * i;
        #pragma unroll
        for (int j = 0; j < 8; j++)
            out[(b * Nn + n) * Dd + d0 + dt + 16 * j] = acc[i][j];
    }
}

// ---------------- K11: metrics ----------------
__global__ __launch_bounds__(256) void metrics_kernel(float* __restrict__ out, int moff) {
    int t = threadIdx.x;
    __shared__ float red[8];
    float s = 0.f;
    #pragma unroll
    for (int i = 0; i < 16; i++) s += g_rC[t + 256 * i];
    float sumR2 = block_sum256(s, red, t);
    float sd = (t < Bb * Ee) ? g_diagC[t] : 0.f;
    float sumDiag = block_sum256(sd, red, t);
    float s2 = (t < Bb * Ee) ? g_rD[t] : 0.f;
    float sumD2 = block_sum256(s2, red, t);
    float s0 = (t < Bb) ? g_rD[t * Ee] : 0.f;
    float sumD0 = block_sum256(s0, red, t);
    if (t == 0) {
        out[moff]     = (sumR2 - sumDiag) / (float)(Bb * Nn * (Nn - 1));
        out[moff + 1] = (sumD2 - sumD0) / (float)(Bb * Ee * (Ee * 1 - 1));
    }
}

// ---------------- launch ----------------
extern "C" void kernel_launch(void* const* d_in, const int* in_sizes, int n_in,
                              void* d_out, int out_size) {
    const float* x   = (const float*)d_in[0];
    const float* phi = (const float*)d_in[1];
    const float* kg  = (const float*)d_in[2];
    const float* kb  = (const float*)d_in[3];
    const float* qg  = (const float*)d_in[4];
    const float* qb  = (const float*)d_in[5];
    const float* lng = (const float*)d_in[6];
    const float* lnb = (const float*)d_in[7];
    const float* sc  = (const float*)d_in[8];
    const float* w1  = (const float*)d_in[9];
    const float* b1  = (const float*)d_in[10];
    const float* w2  = (const float*)d_in[11];
    const float* b2  = (const float*)d_in[12];
    float* out = (float*)d_out;

    q_kernel<<<32, 256>>>(phi, qg, qb, lng, lnb, sc);
    logits_kernel<<<128, 256>>>(x, kg, kb);
    dispatch_kernel<<<dim3(Ee, Bb), 256>>>();
    slots_partial_kernel<<<dim3(4, 32, Bb), 256>>>(x);
    slots_reduce_kernel<<<128, 256>>>();
    mlp1_kernel<<<dim3(4, Ee, 4), 256>>>(w1);
    h1_reduce_kernel<<<512, 256>>>(b1);
    mlp2_kernel<<<dim3(16, Ee), 256>>>(w2);
    p2_reduce_kernel<<<128, 256>>>(b2);
    combine_kernel<<<dim3(8, 16, Bb), 256>>>(out);
    metrics_kernel<<<1, 256>>>(out, out_size - 2);
}